// round 9
// baseline (speedup 1.0000x reference)
#include <cuda_runtime.h>

typedef unsigned long long u64;

#define TW 59
#define TH 32
#define HIN 128
#define WIN 128
#define HOUT 236
#define WOUT 236
#define C1F 0.84852813742385702928f   // 0.6*sqrt(2)
#define C2F 0.56568542494923801952f   // 0.4*sqrt(2)
#define T1P 136
#define INP 39
#define SMP 130
#define ABSM 0x7FFFFFFF7FFFFFFFULL

__device__ __forceinline__ u64 pk2(float lo, float hi) {
    u64 r; asm("mov.b64 %0,{%1,%2};" : "=l"(r) : "f"(lo), "f"(hi)); return r;
}
__device__ __forceinline__ void upk2(float& lo, float& hi, u64 p) {
    asm("mov.b64 {%0,%1},%2;" : "=f"(lo), "=f"(hi) : "l"(p));
}
__device__ __forceinline__ u64 fma2(u64 a, u64 b, u64 c) {
    u64 r; asm("fma.rn.f32x2 %0,%1,%2,%3;" : "=l"(r) : "l"(a), "l"(b), "l"(c)); return r;
}
__device__ __forceinline__ u64 mul2(u64 a, u64 b) {
    u64 r; asm("mul.rn.f32x2 %0,%1,%2;" : "=l"(r) : "l"(a), "l"(b)); return r;
}

// Fused vertical pass, one polyphase block: z rows zi = ZI0+4k (tile-quarter-local),
// z = sum_j ku[4j+p]*vin[m0-j]; lrelu*sqrt2; scatter into 8 output accumulators
// (down-filter even symmetry: coeff index u=min(t,11-t), validated R4/R6).
template<int ZI0, int NZ>
__device__ __forceinline__ void phase_pass(const u64* vin, u64* acc, const u64* kdp,
                                           unsigned kaddr, u64 C1P, u64 C2P)
{
    u64 kc[6];
    #pragma unroll
    for (int j = 0; j < 6; j++)
        asm volatile("ld.shared.b64 %0,[%1];" : "=l"(kc[j]) : "r"(kaddr + 8u * j));
    #pragma unroll
    for (int k = 0; k < NZ; k++) {
        const int zi = ZI0 + 4 * k;
        const int m0 = ((zi + 25) >> 2) - 1;          // in [5,11]
        u64 a = mul2(vin[m0], kc[0]);
        #pragma unroll
        for (int j = 1; j < 6; j++) a = fma2(vin[m0 - j], kc[j], a);
        u64 t  = mul2(a, C1P);
        u64 zz = fma2(a & ABSM, C2P, t);              // packed lrelu*sqrt2
        #pragma unroll
        for (int l = 0; l < 8; l++) {
            if (zi >= 2 * l && zi <= 2 * l + 11) {
                const int tt = zi - 2 * l;
                const int u  = tt < 6 ? tt : 11 - tt;
                acc[l] = fma2(zz, kdp[u], acc[l]);
            }
        }
    }
}

// Polyphase algebra (global coords, verified R1-R6):
//   z col Zg: phase=(Zg+2)&3, input cols ((Zg+10)>>2)-j, j=0..5 ; same vertically.
//   out col Xg reads z cols [2*Xg+15, 2*Xg+26].

__global__ __launch_bounds__(256, 3) void afa_kernel(
    const float* __restrict__ x, const float* __restrict__ bias,
    const float* __restrict__ kup, const float* __restrict__ kdn,
    float* __restrict__ out)
{
    __shared__ __align__(16) float sT1[24 * T1P];   // H-up result (col+4); aliased later as sOut[32][61]
    __shared__ float sIN[24 * INP];                 // input patch (+bias)
    __shared__ __align__(16) float sM[32 * SMP];    // after fused vertical stage
    __shared__ u64 skuP[24];                        // [p*6+j] = pk2(ku[4j+p])
    __shared__ u64 skuA[6], skuB[6];                // (ku[4j],ku[4j+1]) / (ku[4j+2],ku[4j+3])
    __shared__ u64 skdP[6];                         // pk2(kd[u]) (symmetric half)
    __shared__ float skd[12];

    const int tid = threadIdx.x;
    const int bz  = blockIdx.z;
    const int y0  = blockIdx.y * TH;
    const int x0  = blockIdx.x * TW;

    // ---- coefficient prep ----
    if (tid < 6) {
        int j = tid;
        float k0 = kup[4 * j], k1 = kup[4 * j + 1], k2 = kup[4 * j + 2], k3 = kup[4 * j + 3];
        skuA[j] = pk2(k0, k1); skuB[j] = pk2(k2, k3);
        skuP[j] = pk2(k0, k0); skuP[6 + j] = pk2(k1, k1);
        skuP[12 + j] = pk2(k2, k2); skuP[18 + j] = pk2(k3, k3);
    } else if (tid < 12) {
        float v = kdn[tid - 6]; skdP[tid - 6] = pk2(v, v);
    } else if (tid < 24) {
        skd[tid - 12] = kdn[tid - 12];
    }

    const int Zbase = 2 * x0 + 15;
    const int smin  = (Zbase + 10) >> 2;
    const int IC0   = smin - 5;
    const int IR0   = (y0 >> 1) + 1;
    const int off   = 4 * smin - 10 - Zbase;   // -1 or -3

    const float bv = bias[bz & 255];
    const float* __restrict__ xp = x + (long long)bz * (HIN * WIN);

    // ---- Stage 1: load 24x38 input patch + bias ----
    {
        const int c = tid & 31;
        #pragma unroll
        for (int r = tid >> 5; r < 24; r += 8) {
            const int gr = min(IR0 + r, HIN - 1) * WIN;
            sIN[r * INP + c] = xp[gr + min(IC0 + c, WIN - 1)] + bv;
            if (c < 6)
                sIN[r * INP + c + 32] = xp[gr + min(IC0 + c + 32, WIN - 1)] + bv;
        }
    }
    __syncthreads();

    // ---- Stage 2: horizontal 4x upsample, packed output pairs ----
    {
        u64 kA[6], kB[6];
        #pragma unroll
        for (int j = 0; j < 6; j++) { kA[j] = skuA[j]; kB[j] = skuB[j]; }
        for (int idx = tid; idx < 33 * 24; idx += 256) {
            int n  = idx % 24;             // lanes walk rows; pitch 39 conflict-free
            int si = idx / 24;
            float v0 = sIN[n * INP + si + 5];
            u64 vp = pk2(v0, v0);
            u64 accA = mul2(vp, kA[0]), accB = mul2(vp, kB[0]);
            #pragma unroll
            for (int j = 1; j < 6; j++) {
                float v = sIN[n * INP + si + 5 - j];
                vp = pk2(v, v);
                accA = fma2(vp, kA[j], accA);
                accB = fma2(vp, kB[j], accB);
            }
            float a0, a1, a2, a3;
            upk2(a0, a1, accA); upk2(a2, a3, accB);
            int cb = 4 * si + off + 4;     // odd in [1,131]
            sT1[n * T1P + cb] = a0;
            *(u64*)&sT1[n * T1P + cb + 1] = pk2(a1, a2);   // even addr -> STS.64
            sT1[n * T1P + cb + 3] = a3;
        }
    }
    __syncthreads();

    // ---- Stage 3 (fused, packed): V-up + lrelu*sqrt2 + V-down, register resident ----
    {
        const int g   = tid >> 6;          // row quarter: outputs yl = 8g..8g+7
        const int cp  = tid & 63;          // column pair
        const int cc4 = 2 * cp + 4;

        u64 vin[12];
        #pragma unroll
        for (int r = 0; r < 12; r++)
            vin[r] = *(const u64*)&sT1[(4 * g + r) * T1P + cc4];

        u64 kdp[6];
        #pragma unroll
        for (int u = 0; u < 6; u++) kdp[u] = skdP[u];

        const u64 C1P = pk2(C1F, C1F), C2P = pk2(C2F, C2F);

        u64 acc[8];
        #pragma unroll
        for (int l = 0; l < 8; l++) acc[l] = 0ULL;

        unsigned kbase = (unsigned)__cvta_generic_to_shared(&skuP[0]);
        // zi ≡ p-1 (mod 4): phase p handles zi0 = (p+3)&3
        phase_pass<0, 7>(vin, acc, kdp, kbase + 1 * 48, C1P, C2P);  // phase 1
        phase_pass<1, 7>(vin, acc, kdp, kbase + 2 * 48, C1P, C2P);  // phase 2
        phase_pass<2, 6>(vin, acc, kdp, kbase + 3 * 48, C1P, C2P);  // phase 3
        phase_pass<3, 6>(vin, acc, kdp, kbase + 0 * 48, C1P, C2P);  // phase 0

        #pragma unroll
        for (int l = 0; l < 8; l++)
            *(u64*)&sM[(8 * g + l) * SMP + 2 * cp] = acc[l];
    }
    __syncthreads();

    // ---- Stage 4: horizontal 2x downsample (reads sM, writes sOut = sT1 alias) ----
    {
        float kd[12];
        #pragma unroll
        for (int i = 0; i < 12; i++) kd[i] = skd[i];
        float (*so)[61] = (float (*)[61])sT1;
        for (int idx = tid; idx < 15 * 32; idx += 256) {
            int g = idx >> 5, yl = idx & 31;           // lanes walk yl; even pitch -> LDS.64
            const float2* __restrict__ row2 = (const float2*)&sM[yl * SMP + 8 * g];
            float r[18];
            #pragma unroll
            for (int k = 0; k < 9; k++) {
                float2 v = row2[k];
                r[2 * k] = v.x; r[2 * k + 1] = v.y;
            }
            #pragma unroll
            for (int q = 0; q < 4; q++) {
                int xl = 4 * g + q;
                if (xl < TW) {
                    float acc = 0.f;
                    #pragma unroll
                    for (int t = 0; t < 12; t++) acc += kd[t] * r[2 * q + 11 - t];
                    so[yl][xl] = acc;
                }
            }
        }
    }
    __syncthreads();

    // ---- Stage 5: coalesced store ----
    {
        float* __restrict__ op = out + (long long)bz * (HOUT * WOUT);
        float (*so)[61] = (float (*)[61])sT1;
        for (int idx = tid; idx < TH * TW; idx += 256) {
            int yl = idx / TW, xl = idx - yl * TW;
            int yg = y0 + yl;
            if (yg < HOUT) op[yg * WOUT + x0 + xl] = so[yl][xl];
        }
    }
}

extern "C" void kernel_launch(void* const* d_in, const int* in_sizes, int n_in,
                              void* d_out, int out_size)
{
    const float* x   = (const float*)d_in[0];
    const float* b   = (const float*)d_in[1];
    const float* kup = (const float*)d_in[2];
    const float* kdn = (const float*)d_in[3];
    float* out = (float*)d_out;

    dim3 grid(WOUT / TW, (HOUT + TH - 1) / TH, 4 * 256);   // 4 x 8 x 1024
    afa_kernel<<<grid, 256>>>(x, b, kup, kdn, out);
}

// round 16
// speedup vs baseline: 1.2366x; 1.2366x over previous
#include <cuda_runtime.h>

#define TW 59
#define TH 32
#define ZC 128
#define NIR 24
#define NIC 38
#define HIN 128
#define WIN 128
#define HOUT 236
#define WOUT 236
#define C1F 0.84852813742385702928f   // 0.6*sqrt(2)
#define C2F 0.56568542494923801952f   // 0.4*sqrt(2)

// Polyphase algebra (global coords, verified R1-R9):
//   z col Zg: phase=(Zg+2)&3, input cols ((Zg+10)>>2)-j, j=0..5 ; same vertically.
//   out col Xg reads z cols [2*Xg+15, 2*Xg+26].
// Tile: outputs [y0,y0+32) x [x0,x0+59); local z col cc = Zg-(2*x0+15).

__global__ __launch_bounds__(256, 4) void afa_kernel(
    const float* __restrict__ x, const float* __restrict__ bias,
    const float* __restrict__ kup, const float* __restrict__ kdn,
    float* __restrict__ out)
{
    __shared__ float sIN[NIR][39];    // input patch (+bias)
    __shared__ float sT1[NIR][137];   // after H-up (stored at col+3); aliased later as sOut[32][61]
    __shared__ float sM [TH ][130];   // after fused V-up/lrelu/V-down (even pitch -> LDS.64)
    __shared__ float sku[24];
    __shared__ float skd[12];

    const int tid = threadIdx.x;
    const int bz  = blockIdx.z;
    const int y0  = blockIdx.y * TH;
    const int x0  = blockIdx.x * TW;

    if (tid < 24)       sku[tid]      = kup[tid];
    else if (tid < 36)  skd[tid - 24] = kdn[tid - 24];

    const int Zbase = 2 * x0 + 15;
    const int smin  = (Zbase + 10) >> 2;
    const int IC0   = smin - 5;
    const int IR0   = (y0 >> 1) + 1;
    const int off   = 4 * smin - 10 - Zbase;   // -1 or -3

    const float bv = bias[bz & 255];
    const float* __restrict__ xp = x + (long long)bz * (HIN * WIN);

    // ---- Stage 1: load 24x38 input patch + bias (division-free) ----
    {
        const int c = tid & 31;
        #pragma unroll
        for (int r = tid >> 5; r < NIR; r += 8) {
            const int gr = min(IR0 + r, HIN - 1) * WIN;
            sIN[r][c] = xp[gr + min(IC0 + c, WIN - 1)] + bv;
            if (c < NIC - 32)
                sIN[r][c + 32] = xp[gr + min(IC0 + c + 32, WIN - 1)] + bv;
        }
    }
    __syncthreads();

    float ku[24];
    #pragma unroll
    for (int i = 0; i < 24; i++) ku[i] = sku[i];
    float kd[6];                       // 12-tap down filter is even-symmetric
    #pragma unroll
    for (int i = 0; i < 6; i++) kd[i] = skd[i];

    // ---- Stage 2: horizontal 4x upsample, phase-blocked, unconditional stores ----
    for (int idx = tid; idx < 33 * 24; idx += 256) {
        int n  = idx % 24;             // lanes walk rows; pitch 39 conflict-free
        int si = idx / 24;
        float a0 = 0.f, a1 = 0.f, a2 = 0.f, a3 = 0.f;
        #pragma unroll
        for (int j = 0; j < 6; j++) {
            float v = sIN[n][si + 5 - j];
            a0 += ku[4 * j + 0] * v;
            a1 += ku[4 * j + 1] * v;
            a2 += ku[4 * j + 2] * v;
            a3 += ku[4 * j + 3] * v;
        }
        int cb = 4 * si + off + 3;     // in [0, 132]
        sT1[n][cb + 0] = a0;
        sT1[n][cb + 1] = a1;
        sT1[n][cb + 2] = a2;
        sT1[n][cb + 3] = a3;
    }
    __syncthreads();

    // ---- Stage 3 (register pipeline): V-up + lrelu*sqrt2 + V-down ----
    // Rolling 10-slot input window (static %10 indexing under full unroll).
    {
        const int cc = (tid & 127) + 3;    // +3 matches shifted sT1 storage
        const int h  = tid >> 7;           // outputs yl = 16h..16h+15
        float vb[10];
        #pragma unroll
        for (int r = 0; r < 8; r++) vb[r] = sT1[8 * h + r][cc];

        // z local index ii: phase=(ii+1)&3, src row ((ii+25)>>2)-1-j
        float zw[12];
        #pragma unroll
        for (int ii = 0; ii < 10; ii++) {
            const int rv = (ii + 1) & 3, mr = ((ii + 25) >> 2) - 1;   // mr <= 7
            float a = 0.f;
            #pragma unroll
            for (int j = 0; j < 6; j++) a += ku[4 * j + rv] * vb[(mr - j) % 10];
            zw[ii % 12] = fmaf(C2F, fabsf(a), C1F * a);   // lrelu*sqrt2, branch-free
        }
        #pragma unroll
        for (int l = 0; l < 16; l++) {
            if ((l & 1) == 0)              // load row (l/2)+8 into its slot
                vb[(((l >> 1) + 8)) % 10] = sT1[8 * h + (l >> 1) + 8][cc];
            #pragma unroll
            for (int p = 0; p < 2; p++) {
                const int ii = 2 * l + 10 + p;
                const int rv = (ii + 1) & 3, mr = ((ii + 25) >> 2) - 1;
                float a = 0.f;
                #pragma unroll
                for (int j = 0; j < 6; j++) a += ku[4 * j + rv] * vb[(mr - j) % 10];
                zw[ii % 12] = fmaf(C2F, fabsf(a), C1F * a);
            }
            float acc = 0.f;
            #pragma unroll
            for (int t = 0; t < 12; t++)
                acc += kd[t < 6 ? t : 11 - t] * zw[(2 * l + 11 - t) % 12];
            sM[16 * h + l][cc - 3] = acc;
        }
    }
    __syncthreads();

    // ---- Stage 4: horizontal 2x downsample, LDS.64 reads ----
    float (*sOut)[61] = (float (*)[61]) & sT1[0][0];   // alias sT1 storage
    for (int idx = tid; idx < 15 * 32; idx += 256) {
        int g = idx >> 5, yl = idx & 31;   // lanes walk yl: even pitch 130, conflict-free .64
        const float2* __restrict__ row2 =
            (const float2*)&sM[yl][8 * g];              // 8g even, pitch even -> aligned
        float r[18];
        #pragma unroll
        for (int k = 0; k < 9; k++) {
            float2 v = row2[k];
            r[2 * k] = v.x; r[2 * k + 1] = v.y;
        }
        #pragma unroll
        for (int q = 0; q < 4; q++) {
            int xl = 4 * g + q;
            if (xl < TW) {
                float acc = 0.f;
                #pragma unroll
                for (int t = 0; t < 12; t++)
                    acc += kd[t < 6 ? t : 11 - t] * r[2 * q + 11 - t];
                sOut[yl][xl] = acc;
            }
        }
    }
    __syncthreads();

    // ---- Stage 5: coalesced store (division-free: 32 rows x 64 lanes) ----
    {
        float* __restrict__ op = out + (long long)bz * (HOUT * WOUT);
        #pragma unroll
        for (int it = 0; it < 8; it++) {
            int idx = tid + 256 * it;      // over 32 x 64
            int yl  = idx >> 6, xl = idx & 63;
            int yg  = y0 + yl;
            if (xl < TW && yg < HOUT)
                op[yg * WOUT + x0 + xl] = sOut[yl][xl];
        }
    }
}

extern "C" void kernel_launch(void* const* d_in, const int* in_sizes, int n_in,
                              void* d_out, int out_size)
{
    const float* x   = (const float*)d_in[0];
    const float* b   = (const float*)d_in[1];
    const float* kup = (const float*)d_in[2];
    const float* kdn = (const float*)d_in[3];
    float* out = (float*)d_out;

    dim3 grid(WOUT / TW, (HOUT + TH - 1) / TH, 4 * 256);   // 4 x 8 x 1024
    afa_kernel<<<grid, 256>>>(x, b, kup, kdn, out);
}